// round 1
// baseline (speedup 1.0000x reference)
#include <cuda_runtime.h>
#include <math.h>

// Problem dims
#define BB   4
#define SS   2048
#define FF   512
#define HH   8
#define DKK  64
#define DVV  64
#define FILT 512

// Scratch (allocation-free rule: __device__ globals)
__device__ float g_Q[BB*HH*SS*DKK];      // [b,h,s,dk]
__device__ float g_K[BB*HH*SS*DKK];
__device__ float g_V[BB*HH*SS*DVV];
__device__ float g_att[BB*SS*HH*DVV];    // [b,s,h*dv] concat layout

// ---------------------------------------------------------------------------
// Projection GEMM: out[b,h,s,:] = X[b,s,:] @ W[h,:,:] + bias[h,:]
// per block: 128 rows x 64 cols, 256 threads, 8x4 microtile, BK=32
// ---------------------------------------------------------------------------
__global__ __launch_bounds__(256) void proj_kernel(
    const float* __restrict__ X,    // [B,S,F]
    const float* __restrict__ W,    // [H,F,64]
    const float* __restrict__ bias, // [H,64]
    float* __restrict__ out)        // [B,H,S,64]
{
    const int b    = blockIdx.z;
    const int h    = blockIdx.y;
    const int row0 = blockIdx.x * 128;

    __shared__ float sX[128][33];
    __shared__ float sW[32][68];

    const int tid = threadIdx.x;
    const int tx  = tid & 15;   // col group (4 cols)
    const int ty  = tid >> 4;   // row group (8 rows)

    const float* Xb = X + ((size_t)b * SS + row0) * FF;
    const float* Wh = W + (size_t)h * FF * DKK;

    float acc[8][4];
    #pragma unroll
    for (int i = 0; i < 8; i++)
        #pragma unroll
        for (int j = 0; j < 4; j++) acc[i][j] = 0.f;

    for (int kt = 0; kt < FF; kt += 32) {
        // X tile: 128 x 32  (1024 float4)
        #pragma unroll
        for (int p = 0; p < 4; p++) {
            int id = tid + p * 256;
            int r  = id >> 3;
            int c4 = (id & 7) * 4;
            float4 v = *reinterpret_cast<const float4*>(Xb + (size_t)r * FF + kt + c4);
            sX[r][c4 + 0] = v.x; sX[r][c4 + 1] = v.y;
            sX[r][c4 + 2] = v.z; sX[r][c4 + 3] = v.w;
        }
        // W tile: 32 x 64  (512 float4)
        #pragma unroll
        for (int p = 0; p < 2; p++) {
            int id = tid + p * 256;
            int r  = id >> 4;
            int c4 = (id & 15) * 4;
            float4 v = *reinterpret_cast<const float4*>(Wh + (size_t)(kt + r) * DKK + c4);
            sW[r][c4 + 0] = v.x; sW[r][c4 + 1] = v.y;
            sW[r][c4 + 2] = v.z; sW[r][c4 + 3] = v.w;
        }
        __syncthreads();

        #pragma unroll
        for (int kk = 0; kk < 32; kk++) {
            float a[8], w4[4];
            #pragma unroll
            for (int i = 0; i < 8; i++) a[i] = sX[ty * 8 + i][kk];
            #pragma unroll
            for (int j = 0; j < 4; j++) w4[j] = sW[kk][tx * 4 + j];
            #pragma unroll
            for (int i = 0; i < 8; i++)
                #pragma unroll
                for (int j = 0; j < 4; j++)
                    acc[i][j] = fmaf(a[i], w4[j], acc[i][j]);
        }
        __syncthreads();
    }

    float bv[4];
    #pragma unroll
    for (int j = 0; j < 4; j++) bv[j] = bias[h * DKK + tx * 4 + j];

    float* O = out + (((size_t)b * HH + h) * SS + row0) * DKK;
    #pragma unroll
    for (int i = 0; i < 8; i++) {
        int r = ty * 8 + i;
        #pragma unroll
        for (int j = 0; j < 4; j++)
            O[(size_t)r * DKK + tx * 4 + j] = acc[i][j] + bv[j];
    }
}

// ---------------------------------------------------------------------------
// Flash attention: per (b,h), Br=64 query rows per block, Bc=32 key cols/iter
// 256 threads: 16x16 grid. scores: 4 rows x 2 cols/thread. O: 4 rows x 4 cols.
// writes directly to concat layout g_att[b][s][h*64+v].
// ---------------------------------------------------------------------------
__global__ __launch_bounds__(256) void attn_kernel()
{
    const int b  = blockIdx.z;
    const int h  = blockIdx.y;
    const int q0 = blockIdx.x * 64;

    const float* Qp = g_Q + (((size_t)b * HH + h) * SS + q0) * DKK;
    const float* Kp = g_K + ((size_t)b * HH + h) * SS * DKK;
    const float* Vp = g_V + ((size_t)b * HH + h) * SS * DVV;

    __shared__ float sQ[64][65];
    __shared__ float sK[32][65];
    __shared__ float sV[32][65];
    __shared__ float sP[64][33];

    const int tid = threadIdx.x;
    const int tx  = tid & 15;
    const int ty  = tid >> 4;

    // Load Q tile (64 x 64)
    #pragma unroll
    for (int p = 0; p < 4; p++) {
        int id = tid + p * 256;
        int r  = id >> 4;
        int c4 = (id & 15) * 4;
        float4 v = *reinterpret_cast<const float4*>(Qp + (size_t)r * DKK + c4);
        sQ[r][c4 + 0] = v.x; sQ[r][c4 + 1] = v.y;
        sQ[r][c4 + 2] = v.z; sQ[r][c4 + 3] = v.w;
    }
    __syncthreads();

    float m[4], l[4], o[4][4];
    #pragma unroll
    for (int i = 0; i < 4; i++) {
        m[i] = -1e30f; l[i] = 0.f;
        #pragma unroll
        for (int j = 0; j < 4; j++) o[i][j] = 0.f;
    }

    const float scale = 0.125f; // 1/sqrt(64)

    for (int kt = 0; kt < SS; kt += 32) {
        // Load K,V tiles (32 x 64 each)
        #pragma unroll
        for (int p = 0; p < 2; p++) {
            int id = tid + p * 256;
            int r  = id >> 4;
            int c4 = (id & 15) * 4;
            float4 kv = *reinterpret_cast<const float4*>(Kp + (size_t)(kt + r) * DKK + c4);
            sK[r][c4 + 0] = kv.x; sK[r][c4 + 1] = kv.y;
            sK[r][c4 + 2] = kv.z; sK[r][c4 + 3] = kv.w;
            float4 vv = *reinterpret_cast<const float4*>(Vp + (size_t)(kt + r) * DVV + c4);
            sV[r][c4 + 0] = vv.x; sV[r][c4 + 1] = vv.y;
            sV[r][c4 + 2] = vv.z; sV[r][c4 + 3] = vv.w;
        }
        __syncthreads();

        // scores: s[i][j] = Q[ty*4+i,:] . K[tx*2+j,:]
        float s[4][2];
        #pragma unroll
        for (int i = 0; i < 4; i++) { s[i][0] = 0.f; s[i][1] = 0.f; }
        #pragma unroll 8
        for (int d = 0; d < DKK; d++) {
            float q[4], k[2];
            #pragma unroll
            for (int i = 0; i < 4; i++) q[i] = sQ[ty * 4 + i][d];
            k[0] = sK[tx * 2 + 0][d];
            k[1] = sK[tx * 2 + 1][d];
            #pragma unroll
            for (int i = 0; i < 4; i++) {
                s[i][0] = fmaf(q[i], k[0], s[i][0]);
                s[i][1] = fmaf(q[i], k[1], s[i][1]);
            }
        }

        // online softmax update (row stats across the 16 tx threads)
        float alpha[4];
        #pragma unroll
        for (int i = 0; i < 4; i++) {
            s[i][0] *= scale; s[i][1] *= scale;
            float mt = fmaxf(s[i][0], s[i][1]);
            #pragma unroll
            for (int off = 8; off >= 1; off >>= 1)
                mt = fmaxf(mt, __shfl_xor_sync(0xffffffffu, mt, off));
            float mn = fmaxf(m[i], mt);
            alpha[i] = __expf(m[i] - mn);
            m[i] = mn;
            float p0 = __expf(s[i][0] - mn);
            float p1 = __expf(s[i][1] - mn);
            float rs = p0 + p1;
            #pragma unroll
            for (int off = 8; off >= 1; off >>= 1)
                rs += __shfl_xor_sync(0xffffffffu, rs, off);
            l[i] = l[i] * alpha[i] + rs;
            sP[ty * 4 + i][tx * 2 + 0] = p0;
            sP[ty * 4 + i][tx * 2 + 1] = p1;
            #pragma unroll
            for (int j = 0; j < 4; j++) o[i][j] *= alpha[i];
        }
        __syncthreads();

        // o += P @ V  (rows ty*4+i, V cols tx*4+j)
        #pragma unroll 8
        for (int c = 0; c < 32; c++) {
            float pv[4], vv[4];
            #pragma unroll
            for (int i = 0; i < 4; i++) pv[i] = sP[ty * 4 + i][c];
            #pragma unroll
            for (int j = 0; j < 4; j++) vv[j] = sV[c][tx * 4 + j];
            #pragma unroll
            for (int i = 0; i < 4; i++)
                #pragma unroll
                for (int j = 0; j < 4; j++)
                    o[i][j] = fmaf(pv[i], vv[j], o[i][j]);
        }
        __syncthreads();
    }

    // normalize + write to concat layout [b, s, h*64 + v]
    #pragma unroll
    for (int i = 0; i < 4; i++) {
        float inv = 1.f / l[i];
        int r = q0 + ty * 4 + i;
        float* dst = g_att + ((size_t)b * SS + r) * (HH * DVV) + h * DVV + tx * 4;
        #pragma unroll
        for (int j = 0; j < 4; j++) dst[j] = o[i][j] * inv;
    }
}

// ---------------------------------------------------------------------------
// Output GEMM: out[M,512] = att[M,512] @ Wo[512,512] + bo
// per block: 128 rows x 64 cols, 256 threads, 8x4 microtile
// ---------------------------------------------------------------------------
__global__ __launch_bounds__(256) void out_gemm_kernel(
    const float* __restrict__ A,   // [M, 512]
    const float* __restrict__ Wo,  // [512, 512]
    const float* __restrict__ bo,  // [512]
    float* __restrict__ out)       // [M, 512]
{
    const int row0 = blockIdx.x * 128;
    const int col0 = blockIdx.y * 64;

    __shared__ float sA[128][33];
    __shared__ float sB[32][68];

    const int tid = threadIdx.x;
    const int tx  = tid & 15;
    const int ty  = tid >> 4;

    float acc[8][4];
    #pragma unroll
    for (int i = 0; i < 8; i++)
        #pragma unroll
        for (int j = 0; j < 4; j++) acc[i][j] = 0.f;

    for (int kt = 0; kt < FF; kt += 32) {
        #pragma unroll
        for (int p = 0; p < 4; p++) {
            int id = tid + p * 256;
            int r  = id >> 3;
            int c4 = (id & 7) * 4;
            float4 v = *reinterpret_cast<const float4*>(A + (size_t)(row0 + r) * FF + kt + c4);
            sA[r][c4 + 0] = v.x; sA[r][c4 + 1] = v.y;
            sA[r][c4 + 2] = v.z; sA[r][c4 + 3] = v.w;
        }
        #pragma unroll
        for (int p = 0; p < 2; p++) {
            int id = tid + p * 256;
            int r  = id >> 4;
            int c4 = (id & 15) * 4;
            float4 v = *reinterpret_cast<const float4*>(Wo + (size_t)(kt + r) * FILT + col0 + c4);
            sB[r][c4 + 0] = v.x; sB[r][c4 + 1] = v.y;
            sB[r][c4 + 2] = v.z; sB[r][c4 + 3] = v.w;
        }
        __syncthreads();

        #pragma unroll
        for (int kk = 0; kk < 32; kk++) {
            float a[8], w4[4];
            #pragma unroll
            for (int i = 0; i < 8; i++) a[i] = sA[ty * 8 + i][kk];
            #pragma unroll
            for (int j = 0; j < 4; j++) w4[j] = sB[kk][tx * 4 + j];
            #pragma unroll
            for (int i = 0; i < 8; i++)
                #pragma unroll
                for (int j = 0; j < 4; j++)
                    acc[i][j] = fmaf(a[i], w4[j], acc[i][j]);
        }
        __syncthreads();
    }

    float bv[4];
    #pragma unroll
    for (int j = 0; j < 4; j++) bv[j] = bo[col0 + tx * 4 + j];

    #pragma unroll
    for (int i = 0; i < 8; i++) {
        int r = row0 + ty * 8 + i;
        #pragma unroll
        for (int j = 0; j < 4; j++)
            out[(size_t)r * FILT + col0 + tx * 4 + j] = acc[i][j] + bv[j];
    }
}

// ---------------------------------------------------------------------------
extern "C" void kernel_launch(void* const* d_in, const int* in_sizes, int n_in,
                              void* d_out, int out_size)
{
    const float* x_q = (const float*)d_in[0];
    const float* x_k = (const float*)d_in[1];
    const float* x_v = (const float*)d_in[2];
    const float* Wq  = (const float*)d_in[3];
    const float* bq  = (const float*)d_in[4];
    const float* Wk  = (const float*)d_in[5];
    const float* bk  = (const float*)d_in[6];
    const float* Wv  = (const float*)d_in[7];
    const float* bv  = (const float*)d_in[8];
    const float* Wo  = (const float*)d_in[9];
    const float* bo  = (const float*)d_in[10];
    float* out = (float*)d_out;

    float *Qp, *Kp, *Vp, *Ap;
    cudaGetSymbolAddress((void**)&Qp, g_Q);
    cudaGetSymbolAddress((void**)&Kp, g_K);
    cudaGetSymbolAddress((void**)&Vp, g_V);
    cudaGetSymbolAddress((void**)&Ap, g_att);

    dim3 gproj(SS / 128, HH, BB);
    proj_kernel<<<gproj, 256>>>(x_q, Wq, bq, Qp);
    proj_kernel<<<gproj, 256>>>(x_k, Wk, bk, Kp);
    proj_kernel<<<gproj, 256>>>(x_v, Wv, bv, Vp);

    dim3 gattn(SS / 64, HH, BB);
    attn_kernel<<<gattn, 256>>>();

    dim3 gout((BB * SS) / 128, FILT / 64);
    out_gemm_kernel<<<gout, 256>>>(Ap, Wo, bo, out);
}

// round 2
// speedup vs baseline: 1.6679x; 1.6679x over previous
#include <cuda_runtime.h>
#include <math.h>

// Problem dims
#define BB   4
#define SS   2048
#define FF   512
#define HH   8
#define DKK  64
#define DVV  64
#define FILT 512

// Scratch (allocation-free rule: __device__ globals)
__device__ float g_Q[BB*HH*SS*DKK];      // [b,h,s,dk]
__device__ float g_K[BB*HH*SS*DKK];
__device__ float g_V[BB*HH*SS*DVV];
__device__ float g_att[BB*SS*HH*DVV];    // [b,s,h*dv] concat layout

// ---------------------------------------------------------------------------
// helpers
// ---------------------------------------------------------------------------
__device__ __forceinline__ unsigned f2tf(float x) {
    unsigned r;
    asm("cvt.rna.tf32.f32 %0, %1;" : "=r"(r) : "f"(x));
    return r;
}

// exp2 on FMA pipe (no MUFU). Input y <= 0 (may be hugely negative).
__device__ __forceinline__ float exp2_fast(float y) {
    y = fmaxf(y, -126.0f);
    float t = y + 12582912.0f;                 // round-to-nearest-int magic (2^23*1.5)
    float n = t - 12582912.0f;
    float f = y - n;                            // f in [-0.5, 0.5]
    float p = 0.0013333558f;                    // ln2^5/120
    p = fmaf(p, f, 0.0096181291f);              // ln2^4/24
    p = fmaf(p, f, 0.0555041087f);              // ln2^3/6
    p = fmaf(p, f, 0.2402265070f);              // ln2^2/2
    p = fmaf(p, f, 0.6931471806f);              // ln2
    p = fmaf(p, f, 1.0f);
    int ni = __float_as_int(t) - 0x4B400000;    // == (int)n
    float sc = __int_as_float((ni + 127) << 23);
    return p * sc;
}

__device__ __forceinline__ void mma_tf32(float& d0, float& d1, float& d2, float& d3,
                                         unsigned a0, unsigned a1, unsigned a2, unsigned a3,
                                         unsigned b0, unsigned b1) {
    asm("mma.sync.aligned.m16n8k8.row.col.f32.tf32.tf32.f32 "
        "{%0,%1,%2,%3}, {%4,%5,%6,%7}, {%8,%9}, {%0,%1,%2,%3};"
        : "+f"(d0), "+f"(d1), "+f"(d2), "+f"(d3)
        : "r"(a0), "r"(a1), "r"(a2), "r"(a3), "r"(b0), "r"(b1));
}

// ---------------------------------------------------------------------------
// Projection GEMM: out[b,h,s,:] = X[b,s,:] @ W[h,:,:] + bias[h,:]
// ---------------------------------------------------------------------------
__global__ __launch_bounds__(256) void proj_kernel(
    const float* __restrict__ X,    // [B,S,F]
    const float* __restrict__ W,    // [H,F,64]
    const float* __restrict__ bias, // [H,64]
    float* __restrict__ out)        // [B,H,S,64]
{
    const int b    = blockIdx.z;
    const int h    = blockIdx.y;
    const int row0 = blockIdx.x * 128;

    __shared__ float sX[128][33];
    __shared__ float sW[32][68];

    const int tid = threadIdx.x;
    const int tx  = tid & 15;
    const int ty  = tid >> 4;

    const float* Xb = X + ((size_t)b * SS + row0) * FF;
    const float* Wh = W + (size_t)h * FF * DKK;

    float acc[8][4];
    #pragma unroll
    for (int i = 0; i < 8; i++)
        #pragma unroll
        for (int j = 0; j < 4; j++) acc[i][j] = 0.f;

    for (int kt = 0; kt < FF; kt += 32) {
        #pragma unroll
        for (int p = 0; p < 4; p++) {
            int id = tid + p * 256;
            int r  = id >> 3;
            int c4 = (id & 7) * 4;
            float4 v = *reinterpret_cast<const float4*>(Xb + (size_t)r * FF + kt + c4);
            sX[r][c4 + 0] = v.x; sX[r][c4 + 1] = v.y;
            sX[r][c4 + 2] = v.z; sX[r][c4 + 3] = v.w;
        }
        #pragma unroll
        for (int p = 0; p < 2; p++) {
            int id = tid + p * 256;
            int r  = id >> 4;
            int c4 = (id & 15) * 4;
            float4 v = *reinterpret_cast<const float4*>(Wh + (size_t)(kt + r) * DKK + c4);
            sW[r][c4 + 0] = v.x; sW[r][c4 + 1] = v.y;
            sW[r][c4 + 2] = v.z; sW[r][c4 + 3] = v.w;
        }
        __syncthreads();

        #pragma unroll
        for (int kk = 0; kk < 32; kk++) {
            float a[8], w4[4];
            #pragma unroll
            for (int i = 0; i < 8; i++) a[i] = sX[ty * 8 + i][kk];
            #pragma unroll
            for (int j = 0; j < 4; j++) w4[j] = sW[kk][tx * 4 + j];
            #pragma unroll
            for (int i = 0; i < 8; i++)
                #pragma unroll
                for (int j = 0; j < 4; j++)
                    acc[i][j] = fmaf(a[i], w4[j], acc[i][j]);
        }
        __syncthreads();
    }

    float bv[4];
    #pragma unroll
    for (int j = 0; j < 4; j++) bv[j] = bias[h * DKK + tx * 4 + j];

    float* O = out + (((size_t)b * HH + h) * SS + row0) * DKK;
    #pragma unroll
    for (int i = 0; i < 8; i++) {
        int r = ty * 8 + i;
        #pragma unroll
        for (int j = 0; j < 4; j++)
            O[(size_t)r * DKK + tx * 4 + j] = acc[i][j] + bv[j];
    }
}

// ---------------------------------------------------------------------------
// Flash attention via mma.sync tf32 (tensor pipe), exp2 on FMA pipe.
// Block: 256 threads = 8 warps. Br=128 rows/block (16 rows/warp), Bc=64.
// Scores computed in log2 domain (Q pre-scaled by 0.125*log2e).
// ---------------------------------------------------------------------------
__global__ __launch_bounds__(256) void attn_mma_kernel()
{
    const int b  = blockIdx.z;
    const int h  = blockIdx.y;
    const int q0 = blockIdx.x * 128;

    const int tid  = threadIdx.x;
    const int w    = tid >> 5;
    const int lane = tid & 31;
    const int g    = lane >> 2;   // group id (row within 8)
    const int t    = lane & 3;    // thread-in-group

    __shared__ float sK[64][72];
    __shared__ float sV[64][72];

    const float* Qb = g_Q + (((size_t)b * HH + h) * SS + q0 + w * 16) * DKK;
    const float* Kb = g_K + ((size_t)b * HH + h) * SS * DKK;
    const float* Vb = g_V + ((size_t)b * HH + h) * SS * DVV;

    const float QS = 0.125f * 1.4426950408889634f;  // softmax scale * log2(e)

    // Q fragments, register-resident for whole kernel (a-frag per k-step)
    unsigned qa[8][4];
    #pragma unroll
    for (int kk = 0; kk < 8; kk++) {
        qa[kk][0] = f2tf(Qb[(size_t)(g    ) * DKK + kk * 8 + t    ] * QS);
        qa[kk][1] = f2tf(Qb[(size_t)(g + 8) * DKK + kk * 8 + t    ] * QS);
        qa[kk][2] = f2tf(Qb[(size_t)(g    ) * DKK + kk * 8 + t + 4] * QS);
        qa[kk][3] = f2tf(Qb[(size_t)(g + 8) * DKK + kk * 8 + t + 4] * QS);
    }

    float o[8][4];
    #pragma unroll
    for (int vt = 0; vt < 8; vt++)
        #pragma unroll
        for (int j = 0; j < 4; j++) o[vt][j] = 0.f;

    float m0 = -1e30f, m1 = -1e30f, l0 = 0.f, l1 = 0.f;

    for (int kt = 0; kt < SS; kt += 64) {
        // ---- load K/V tiles (64x64 each), convert to tf32 in smem ----
        #pragma unroll
        for (int p = 0; p < 4; p++) {
            int f  = tid + p * 256;
            int r  = f >> 4;
            int c4 = (f & 15) * 4;
            float4 kv = *reinterpret_cast<const float4*>(Kb + (size_t)(kt + r) * DKK + c4);
            kv.x = __uint_as_float(f2tf(kv.x)); kv.y = __uint_as_float(f2tf(kv.y));
            kv.z = __uint_as_float(f2tf(kv.z)); kv.w = __uint_as_float(f2tf(kv.w));
            *reinterpret_cast<float4*>(&sK[r][c4]) = kv;
            float4 vv = *reinterpret_cast<const float4*>(Vb + (size_t)(kt + r) * DVV + c4);
            vv.x = __uint_as_float(f2tf(vv.x)); vv.y = __uint_as_float(f2tf(vv.y));
            vv.z = __uint_as_float(f2tf(vv.z)); vv.w = __uint_as_float(f2tf(vv.w));
            *reinterpret_cast<float4*>(&sV[r][c4]) = vv;
        }
        __syncthreads();

        // ---- scores S(16x64) = Q @ K^T in log2 domain ----
        float s[8][4];
        #pragma unroll
        for (int nt = 0; nt < 8; nt++)
            #pragma unroll
            for (int j = 0; j < 4; j++) s[nt][j] = 0.f;

        #pragma unroll
        for (int kk = 0; kk < 8; kk++) {
            #pragma unroll
            for (int nt = 0; nt < 8; nt++) {
                unsigned b0 = __float_as_uint(sK[nt * 8 + g][kk * 8 + t    ]);
                unsigned b1 = __float_as_uint(sK[nt * 8 + g][kk * 8 + t + 4]);
                mma_tf32(s[nt][0], s[nt][1], s[nt][2], s[nt][3],
                         qa[kk][0], qa[kk][1], qa[kk][2], qa[kk][3], b0, b1);
            }
        }

        // ---- online softmax (base-2) ----
        float rmax0 = -1e30f, rmax1 = -1e30f;
        #pragma unroll
        for (int nt = 0; nt < 8; nt++) {
            rmax0 = fmaxf(rmax0, fmaxf(s[nt][0], s[nt][1]));
            rmax1 = fmaxf(rmax1, fmaxf(s[nt][2], s[nt][3]));
        }
        rmax0 = fmaxf(rmax0, __shfl_xor_sync(0xffffffffu, rmax0, 1));
        rmax0 = fmaxf(rmax0, __shfl_xor_sync(0xffffffffu, rmax0, 2));
        rmax1 = fmaxf(rmax1, __shfl_xor_sync(0xffffffffu, rmax1, 1));
        rmax1 = fmaxf(rmax1, __shfl_xor_sync(0xffffffffu, rmax1, 2));

        float nm0 = fmaxf(m0, rmax0);
        float nm1 = fmaxf(m1, rmax1);
        float al0 = exp2_fast(m0 - nm0);
        float al1 = exp2_fast(m1 - nm1);
        m0 = nm0; m1 = nm1;

        float sum0 = 0.f, sum1 = 0.f;
        #pragma unroll
        for (int nt = 0; nt < 8; nt++) {
            s[nt][0] = exp2_fast(s[nt][0] - m0);
            s[nt][1] = exp2_fast(s[nt][1] - m0);
            s[nt][2] = exp2_fast(s[nt][2] - m1);
            s[nt][3] = exp2_fast(s[nt][3] - m1);
            sum0 += s[nt][0] + s[nt][1];
            sum1 += s[nt][2] + s[nt][3];
        }
        sum0 += __shfl_xor_sync(0xffffffffu, sum0, 1);
        sum0 += __shfl_xor_sync(0xffffffffu, sum0, 2);
        sum1 += __shfl_xor_sync(0xffffffffu, sum1, 1);
        sum1 += __shfl_xor_sync(0xffffffffu, sum1, 2);

        l0 = l0 * al0 + sum0;
        l1 = l1 * al1 + sum1;

        #pragma unroll
        for (int vt = 0; vt < 8; vt++) {
            o[vt][0] *= al0; o[vt][1] *= al0;
            o[vt][2] *= al1; o[vt][3] *= al1;
        }

        // ---- O += P @ V. P tile nt (cols nt*8..+7) is k-step nt of the PV mma ----
        const int srcA = (lane & ~3) | (t >> 1);
        const int srcB = srcA + 2;
        #pragma unroll
        for (int nt = 0; nt < 8; nt++) {
            unsigned u0 = f2tf(s[nt][0]);
            unsigned u1 = f2tf(s[nt][1]);
            unsigned u2 = f2tf(s[nt][2]);
            unsigned u3 = f2tf(s[nt][3]);
            // relayout C-fragment -> A-fragment within each quad
            unsigned x0 = __shfl_sync(0xffffffffu, u0, srcA);
            unsigned x1 = __shfl_sync(0xffffffffu, u1, srcA);
            unsigned pa0 = (t & 1) ? x1 : x0;
            unsigned y0 = __shfl_sync(0xffffffffu, u2, srcA);
            unsigned y1 = __shfl_sync(0xffffffffu, u3, srcA);
            unsigned pa1 = (t & 1) ? y1 : y0;
            x0 = __shfl_sync(0xffffffffu, u0, srcB);
            x1 = __shfl_sync(0xffffffffu, u1, srcB);
            unsigned pa2 = (t & 1) ? x1 : x0;
            y0 = __shfl_sync(0xffffffffu, u2, srcB);
            y1 = __shfl_sync(0xffffffffu, u3, srcB);
            unsigned pa3 = (t & 1) ? y1 : y0;

            #pragma unroll
            for (int vt = 0; vt < 8; vt++) {
                unsigned b0 = __float_as_uint(sV[nt * 8 + t    ][vt * 8 + g]);
                unsigned b1 = __float_as_uint(sV[nt * 8 + t + 4][vt * 8 + g]);
                mma_tf32(o[vt][0], o[vt][1], o[vt][2], o[vt][3],
                         pa0, pa1, pa2, pa3, b0, b1);
            }
        }
        __syncthreads();
    }

    // ---- normalize + write concat layout [b, s, h*64 + v] ----
    float inv0 = 1.f / l0;
    float inv1 = 1.f / l1;
    int r0 = q0 + w * 16 + g;
    int r1 = r0 + 8;
    #pragma unroll
    for (int vt = 0; vt < 8; vt++) {
        float2 v0 = make_float2(o[vt][0] * inv0, o[vt][1] * inv0);
        float2 v1 = make_float2(o[vt][2] * inv1, o[vt][3] * inv1);
        *reinterpret_cast<float2*>(g_att + ((size_t)b * SS + r0) * (HH * DVV) + h * DVV + vt * 8 + 2 * t) = v0;
        *reinterpret_cast<float2*>(g_att + ((size_t)b * SS + r1) * (HH * DVV) + h * DVV + vt * 8 + 2 * t) = v1;
    }
}

// ---------------------------------------------------------------------------
// Output GEMM: out[M,512] = att[M,512] @ Wo[512,512] + bo
// ---------------------------------------------------------------------------
__global__ __launch_bounds__(256) void out_gemm_kernel(
    const float* __restrict__ A,   // [M, 512]
    const float* __restrict__ Wo,  // [512, 512]
    const float* __restrict__ bo,  // [512]
    float* __restrict__ out)       // [M, 512]
{
    const int row0 = blockIdx.x * 128;
    const int col0 = blockIdx.y * 64;

    __shared__ float sA[128][33];
    __shared__ float sB[32][68];

    const int tid = threadIdx.x;
    const int tx  = tid & 15;
    const int ty  = tid >> 4;

    float acc[8][4];
    #pragma unroll
    for (int i = 0; i < 8; i++)
        #pragma unroll
        for (int j = 0; j < 4; j++) acc[i][j] = 0.f;

    for (int kt = 0; kt < FF; kt += 32) {
        #pragma unroll
        for (int p = 0; p < 4; p++) {
            int id = tid + p * 256;
            int r  = id >> 3;
            int c4 = (id & 7) * 4;
            float4 v = *reinterpret_cast<const float4*>(A + (size_t)(row0 + r) * FF + kt + c4);
            sA[r][c4 + 0] = v.x; sA[r][c4 + 1] = v.y;
            sA[r][c4 + 2] = v.z; sA[r][c4 + 3] = v.w;
        }
        #pragma unroll
        for (int p = 0; p < 2; p++) {
            int id = tid + p * 256;
            int r  = id >> 4;
            int c4 = (id & 15) * 4;
            float4 v = *reinterpret_cast<const float4*>(Wo + (size_t)(kt + r) * FILT + col0 + c4);
            sB[r][c4 + 0] = v.x; sB[r][c4 + 1] = v.y;
            sB[r][c4 + 2] = v.z; sB[r][c4 + 3] = v.w;
        }
        __syncthreads();

        #pragma unroll
        for (int kk = 0; kk < 32; kk++) {
            float a[8], w4[4];
            #pragma unroll
            for (int i = 0; i < 8; i++) a[i] = sA[ty * 8 + i][kk];
            #pragma unroll
            for (int j = 0; j < 4; j++) w4[j] = sB[kk][tx * 4 + j];
            #pragma unroll
            for (int i = 0; i < 8; i++)
                #pragma unroll
                for (int j = 0; j < 4; j++)
                    acc[i][j] = fmaf(a[i], w4[j], acc[i][j]);
        }
        __syncthreads();
    }

    float bv[4];
    #pragma unroll
    for (int j = 0; j < 4; j++) bv[j] = bo[col0 + tx * 4 + j];

    #pragma unroll
    for (int i = 0; i < 8; i++) {
        int r = row0 + ty * 8 + i;
        #pragma unroll
        for (int j = 0; j < 4; j++)
            out[(size_t)r * FILT + col0 + tx * 4 + j] = acc[i][j] + bv[j];
    }
}

// ---------------------------------------------------------------------------
extern "C" void kernel_launch(void* const* d_in, const int* in_sizes, int n_in,
                              void* d_out, int out_size)
{
    const float* x_q = (const float*)d_in[0];
    const float* x_k = (const float*)d_in[1];
    const float* x_v = (const float*)d_in[2];
    const float* Wq  = (const float*)d_in[3];
    const float* bq  = (const float*)d_in[4];
    const float* Wk  = (const float*)d_in[5];
    const float* bk  = (const float*)d_in[6];
    const float* Wv  = (const float*)d_in[7];
    const float* bv  = (const float*)d_in[8];
    const float* Wo  = (const float*)d_in[9];
    const float* bo  = (const float*)d_in[10];
    float* out = (float*)d_out;

    float *Qp, *Kp, *Vp, *Ap;
    cudaGetSymbolAddress((void**)&Qp, g_Q);
    cudaGetSymbolAddress((void**)&Kp, g_K);
    cudaGetSymbolAddress((void**)&Vp, g_V);
    cudaGetSymbolAddress((void**)&Ap, g_att);

    dim3 gproj(SS / 128, HH, BB);
    proj_kernel<<<gproj, 256>>>(x_q, Wq, bq, Qp);
    proj_kernel<<<gproj, 256>>>(x_k, Wk, bk, Kp);
    proj_kernel<<<gproj, 256>>>(x_v, Wv, bv, Vp);

    dim3 gattn(SS / 128, HH, BB);
    attn_mma_kernel<<<gattn, 256>>>();

    dim3 gout((BB * SS) / 128, FILT / 64);
    out_gemm_kernel<<<gout, 256>>>(Ap, Wo, bo, out);
}